// round 1
// baseline (speedup 1.0000x reference)
#include <cuda_runtime.h>
#include <cstdint>

// Problem constants
#define BB 8
#define SS 1024
#define DD 768
#define HH 12
#define LL 6
#define DF 3072
#define HD 64
#define TD 2304   // 3*D
#define NROWS (BB*SS)   // 8192

// ---------------- scratch (static device globals; no allocs allowed) -------------
__device__ float g_x[NROWS * DD];                 // residual stream
__device__ float g_h[NROWS * DD];                 // layernorm output
__device__ float g_qkv[NROWS * TD];               // qkv projection
__device__ float g_scores[(size_t)BB * HH * SS * SS];  // attention scores (403MB)
__device__ float g_att[NROWS * DD];               // attention output
__device__ float g_ff[NROWS * DF];                // ff1 output

// ---------------- embedding ------------------------------------------------------
__global__ void embed_kernel(const int* __restrict__ ids,
                             const float* __restrict__ tok,
                             const float* __restrict__ pos,
                             float* __restrict__ x) {
    int idx = blockIdx.x * blockDim.x + threadIdx.x;
    if (idx >= NROWS * DD) return;
    int bs = idx / DD;
    int d  = idx - bs * DD;
    int s  = bs & (SS - 1);
    x[idx] = (tok[(size_t)ids[bs] * DD + d] + pos[s * DD + d]) * 27.712812921102035f;
}

// ---------------- layernorm (block per row, 768 = 256*3) --------------------------
__global__ __launch_bounds__(256) void ln_kernel(const float* __restrict__ x,
                                                 const float* __restrict__ sc,
                                                 const float* __restrict__ bi,
                                                 float* __restrict__ out) {
    int row = blockIdx.x;
    int tid = threadIdx.x;
    const float* p = x + (size_t)row * DD;
    float v0 = p[tid], v1 = p[tid + 256], v2 = p[tid + 512];
    __shared__ float rs[256], rq[256];
    rs[tid] = v0 + v1 + v2;
    rq[tid] = v0 * v0 + v1 * v1 + v2 * v2;
    __syncthreads();
    for (int st = 128; st > 0; st >>= 1) {
        if (tid < st) { rs[tid] += rs[tid + st]; rq[tid] += rq[tid + st]; }
        __syncthreads();
    }
    float mean = rs[0] * (1.0f / DD);
    float var  = rq[0] * (1.0f / DD) - mean * mean;
    float inv  = rsqrtf(var + 1e-5f);
    float* o = out + (size_t)row * DD;
    o[tid]       = (v0 - mean) * inv * sc[tid]       + bi[tid];
    o[tid + 256] = (v1 - mean) * inv * sc[tid + 256] + bi[tid + 256];
    o[tid + 512] = (v2 - mean) * inv * sc[tid + 512] + bi[tid + 512];
}

// ---------------- generic SGEMM: C = A@W + bias (+res)(+relu) ---------------------
// 128x128 tile, BK=8, 256 threads, 8x8 microtile per thread.
template <int RELU, int RES>
__global__ __launch_bounds__(256) void sgemm_kernel(const float* __restrict__ A,
                                                    const float* __restrict__ W,
                                                    const float* __restrict__ bias,
                                                    const float* __restrict__ res,
                                                    float* __restrict__ C,
                                                    int M, int N, int K) {
    __shared__ float As[8][128];
    __shared__ float Bs[8][128];
    const int tid = threadIdx.x;
    const int bm = blockIdx.y * 128;
    const int bn = blockIdx.x * 128;
    const int arow = tid >> 1, acol = (tid & 1) << 2;
    const int brow = tid >> 5, bcol = (tid & 31) << 2;
    const int tx = tid & 15, ty = tid >> 4;
    const float* Ap = A + (size_t)(bm + arow) * K + acol;
    const float* Wp = W + (size_t)brow * N + bn + bcol;
    float acc[8][8];
#pragma unroll
    for (int i = 0; i < 8; i++)
#pragma unroll
        for (int j = 0; j < 8; j++) acc[i][j] = 0.f;

    for (int k0 = 0; k0 < K; k0 += 8) {
        float4 av = *(const float4*)(Ap + k0);
        float4 bv = *(const float4*)(Wp + (size_t)k0 * N);
        As[acol + 0][arow] = av.x;
        As[acol + 1][arow] = av.y;
        As[acol + 2][arow] = av.z;
        As[acol + 3][arow] = av.w;
        *(float4*)(&Bs[brow][bcol]) = bv;
        __syncthreads();
#pragma unroll
        for (int kk = 0; kk < 8; kk++) {
            float a[8], b[8];
            *(float4*)(a)     = *(const float4*)(&As[kk][ty * 4]);
            *(float4*)(a + 4) = *(const float4*)(&As[kk][64 + ty * 4]);
            *(float4*)(b)     = *(const float4*)(&Bs[kk][tx * 4]);
            *(float4*)(b + 4) = *(const float4*)(&Bs[kk][64 + tx * 4]);
#pragma unroll
            for (int i = 0; i < 8; i++)
#pragma unroll
                for (int j = 0; j < 8; j++) acc[i][j] += a[i] * b[j];
        }
        __syncthreads();
    }
#pragma unroll
    for (int i = 0; i < 8; i++) {
        int r = bm + ((i < 4) ? ty * 4 + i : 64 + ty * 4 + (i - 4));
#pragma unroll
        for (int j = 0; j < 8; j++) {
            int c = bn + ((j < 4) ? tx * 4 + j : 64 + tx * 4 + (j - 4));
            float v = acc[i][j] + bias[c];
            if (RELU) v = fmaxf(v, 0.f);
            if (RES) v += res[(size_t)r * N + c];
            C[(size_t)r * N + c] = v;
        }
    }
}

// ---------------- attention scores: 64x64 tile of S x S per (b,h) ----------------
__global__ __launch_bounds__(256) void scores_kernel(const float* __restrict__ qkv,
                                                     const int* __restrict__ mask,
                                                     float* __restrict__ scores) {
    __shared__ float QT[64][64];   // [d][s]
    __shared__ float KT[64][64];   // [d][t]
    int bh = blockIdx.z;
    int b = bh / HH, h = bh % HH;
    int s0 = blockIdx.y * 64, t0 = blockIdx.x * 64;
    int tid = threadIdx.x;
    int lr = tid >> 2, lc = (tid & 3) * 16;
    const float* qb = qkv + (size_t)(b * SS + s0 + lr) * TD + h * 192 + lc;
    const float* kb = qkv + (size_t)(b * SS + t0 + lr) * TD + h * 192 + 64 + lc;
#pragma unroll
    for (int i = 0; i < 4; i++) {
        float4 qv = *(const float4*)(qb + i * 4);
        float4 kv = *(const float4*)(kb + i * 4);
        QT[lc + i * 4 + 0][lr] = qv.x; QT[lc + i * 4 + 1][lr] = qv.y;
        QT[lc + i * 4 + 2][lr] = qv.z; QT[lc + i * 4 + 3][lr] = qv.w;
        KT[lc + i * 4 + 0][lr] = kv.x; KT[lc + i * 4 + 1][lr] = kv.y;
        KT[lc + i * 4 + 2][lr] = kv.z; KT[lc + i * 4 + 3][lr] = kv.w;
    }
    __syncthreads();
    int tx = tid & 15, ty = tid >> 4;
    float acc[4][4];
#pragma unroll
    for (int i = 0; i < 4; i++)
#pragma unroll
        for (int j = 0; j < 4; j++) acc[i][j] = 0.f;
#pragma unroll
    for (int kk = 0; kk < 64; kk++) {
        float4 a = *(const float4*)(&QT[kk][ty * 4]);
        float4 bb = *(const float4*)(&KT[kk][tx * 4]);
        float av[4] = {a.x, a.y, a.z, a.w};
        float bv[4] = {bb.x, bb.y, bb.z, bb.w};
#pragma unroll
        for (int i = 0; i < 4; i++)
#pragma unroll
            for (int j = 0; j < 4; j++) acc[i][j] += av[i] * bv[j];
    }
    // NOTE reference quirk: where mask==1 the score is REPLACED by -1e9.
#pragma unroll
    for (int i = 0; i < 4; i++) {
        int s = s0 + ty * 4 + i;
#pragma unroll
        for (int j = 0; j < 4; j++) {
            int t = t0 + tx * 4 + j;
            float v = (mask[b * SS + t] == 1) ? -1e9f : acc[i][j] * 0.125f;
            scores[((size_t)bh * SS + s) * SS + t] = v;
        }
    }
}

// ---------------- softmax over last dim (row = 1024, block 256) -------------------
__global__ __launch_bounds__(256) void softmax_kernel(float* __restrict__ scores) {
    size_t row = blockIdx.x;
    float* p = scores + row * SS;
    int tid = threadIdx.x;
    float v[4];
#pragma unroll
    for (int i = 0; i < 4; i++) v[i] = p[tid + i * 256];
    float m = fmaxf(fmaxf(v[0], v[1]), fmaxf(v[2], v[3]));
    __shared__ float red[256];
    red[tid] = m;
    __syncthreads();
    for (int st = 128; st > 0; st >>= 1) {
        if (tid < st) red[tid] = fmaxf(red[tid], red[tid + st]);
        __syncthreads();
    }
    float M = red[0];
    __syncthreads();
    float e[4], s = 0.f;
#pragma unroll
    for (int i = 0; i < 4; i++) { e[i] = __expf(v[i] - M); s += e[i]; }
    red[tid] = s;
    __syncthreads();
    for (int st = 128; st > 0; st >>= 1) {
        if (tid < st) red[tid] += red[tid + st];
        __syncthreads();
    }
    float inv = 1.0f / red[0];
#pragma unroll
    for (int i = 0; i < 4; i++) p[tid + i * 256] = e[i] * inv;
}

// ---------------- attn @ V: out 64(s) x 64(hd) tile per (b,h) --------------------
__global__ __launch_bounds__(256) void attnv_kernel(const float* __restrict__ scores,
                                                    const float* __restrict__ qkv,
                                                    float* __restrict__ att) {
    __shared__ float WT[64][64];   // [t][s]
    __shared__ float Vs[64][64];   // [t][hd]
    int bh = blockIdx.y;
    int b = bh / HH, h = bh % HH;
    int s0 = blockIdx.x * 64;
    int tid = threadIdx.x;
    int lr = tid >> 2, lc = (tid & 3) * 16;
    int tx = tid & 15, ty = tid >> 4;
    float acc[4][4];
#pragma unroll
    for (int i = 0; i < 4; i++)
#pragma unroll
        for (int j = 0; j < 4; j++) acc[i][j] = 0.f;

    for (int c0 = 0; c0 < SS; c0 += 64) {
        const float* wb = scores + ((size_t)bh * SS + s0 + lr) * SS + c0 + lc;
        const float* vb = qkv + (size_t)(b * SS + c0 + lr) * TD + h * 192 + 128 + lc;
#pragma unroll
        for (int i = 0; i < 4; i++) {
            float4 wv = *(const float4*)(wb + i * 4);
            WT[lc + i * 4 + 0][lr] = wv.x; WT[lc + i * 4 + 1][lr] = wv.y;
            WT[lc + i * 4 + 2][lr] = wv.z; WT[lc + i * 4 + 3][lr] = wv.w;
            *(float4*)(&Vs[lr][lc + i * 4]) = *(const float4*)(vb + i * 4);
        }
        __syncthreads();
#pragma unroll
        for (int kk = 0; kk < 64; kk++) {
            float4 a = *(const float4*)(&WT[kk][ty * 4]);
            float4 bb = *(const float4*)(&Vs[kk][tx * 4]);
            float av[4] = {a.x, a.y, a.z, a.w};
            float bv[4] = {bb.x, bb.y, bb.z, bb.w};
#pragma unroll
            for (int i = 0; i < 4; i++)
#pragma unroll
                for (int j = 0; j < 4; j++) acc[i][j] += av[i] * bv[j];
        }
        __syncthreads();
    }
#pragma unroll
    for (int i = 0; i < 4; i++) {
        int s = s0 + ty * 4 + i;
#pragma unroll
        for (int j = 0; j < 4; j++)
            att[(size_t)(b * SS + s) * DD + h * 64 + tx * 4 + j] = acc[i][j];
    }
}

// ---------------- final head: LN(x[:,0,:]) @ cls_w + cls_b ------------------------
__global__ __launch_bounds__(256) void head_kernel(const float* __restrict__ x,
                                                   const float* __restrict__ hs,
                                                   const float* __restrict__ hb,
                                                   const float* __restrict__ cw,
                                                   const float* __restrict__ cb,
                                                   float* __restrict__ out) {
    int b = blockIdx.x;
    int tid = threadIdx.x;
    const float* p = x + (size_t)b * SS * DD;   // s = 0 row
    float v0 = p[tid], v1 = p[tid + 256], v2 = p[tid + 512];
    __shared__ float rs[256], rq[256];
    rs[tid] = v0 + v1 + v2;
    rq[tid] = v0 * v0 + v1 * v1 + v2 * v2;
    __syncthreads();
    for (int st = 128; st > 0; st >>= 1) {
        if (tid < st) { rs[tid] += rs[tid + st]; rq[tid] += rq[tid + st]; }
        __syncthreads();
    }
    float mean = rs[0] * (1.0f / DD);
    float var  = rq[0] * (1.0f / DD) - mean * mean;
    float inv  = rsqrtf(var + 1e-5f);
    float p0 = (v0 - mean) * inv * hs[tid]       + hb[tid];
    float p1 = (v1 - mean) * inv * hs[tid + 256] + hb[tid + 256];
    float p2 = (v2 - mean) * inv * hs[tid + 512] + hb[tid + 512];
    float d0 = p0 * cw[2 * tid]     + p1 * cw[2 * (tid + 256)]     + p2 * cw[2 * (tid + 512)];
    float d1 = p0 * cw[2 * tid + 1] + p1 * cw[2 * (tid + 256) + 1] + p2 * cw[2 * (tid + 512) + 1];
    __syncthreads();
    rs[tid] = d0; rq[tid] = d1;
    __syncthreads();
    for (int st = 128; st > 0; st >>= 1) {
        if (tid < st) { rs[tid] += rs[tid + st]; rq[tid] += rq[tid + st]; }
        __syncthreads();
    }
    if (tid == 0) {
        out[2 * b]     = rs[0] + cb[0];
        out[2 * b + 1] = rq[0] + cb[1];
    }
}

// ---------------- host orchestration ---------------------------------------------
extern "C" void kernel_launch(void* const* d_in, const int* in_sizes, int n_in,
                              void* d_out, int out_size) {
    const int*   input_ids = (const int*)d_in[0];
    const int*   attn_mask = (const int*)d_in[1];
    const float* token_emb = (const float*)d_in[2];
    const float* pos_emb   = (const float*)d_in[3];
    const float* qkv_w     = (const float*)d_in[4];
    const float* qkv_b     = (const float*)d_in[5];
    const float* out_w     = (const float*)d_in[6];
    const float* out_b     = (const float*)d_in[7];
    const float* n1_s      = (const float*)d_in[8];
    const float* n1_b      = (const float*)d_in[9];
    const float* ff1_w     = (const float*)d_in[10];
    const float* ff1_b     = (const float*)d_in[11];
    const float* ff2_w     = (const float*)d_in[12];
    const float* ff2_b     = (const float*)d_in[13];
    const float* n2_s      = (const float*)d_in[14];
    const float* n2_b      = (const float*)d_in[15];
    const float* hln_s     = (const float*)d_in[16];
    const float* hln_b     = (const float*)d_in[17];
    const float* cls_w     = (const float*)d_in[18];
    const float* cls_b     = (const float*)d_in[19];
    float* out = (float*)d_out;

    float *x, *h, *qkv, *sc, *att, *ff;
    cudaGetSymbolAddress((void**)&x,   g_x);
    cudaGetSymbolAddress((void**)&h,   g_h);
    cudaGetSymbolAddress((void**)&qkv, g_qkv);
    cudaGetSymbolAddress((void**)&sc,  g_scores);
    cudaGetSymbolAddress((void**)&att, g_att);
    cudaGetSymbolAddress((void**)&ff,  g_ff);

    embed_kernel<<<(NROWS * DD + 255) / 256, 256>>>(input_ids, token_emb, pos_emb, x);

    for (int i = 0; i < LL; i++) {
        ln_kernel<<<NROWS, 256>>>(x, n1_s + i * DD, n1_b + i * DD, h);
        sgemm_kernel<0, 0><<<dim3(TD / 128, NROWS / 128), 256>>>(
            h, qkv_w + (size_t)i * DD * TD, qkv_b + i * TD, nullptr, qkv,
            NROWS, TD, DD);
        scores_kernel<<<dim3(SS / 64, SS / 64, BB * HH), 256>>>(qkv, attn_mask, sc);
        softmax_kernel<<<BB * HH * SS, 256>>>(sc);
        attnv_kernel<<<dim3(SS / 64, BB * HH), 256>>>(sc, qkv, att);
        sgemm_kernel<0, 1><<<dim3(DD / 128, NROWS / 128), 256>>>(
            att, out_w + (size_t)i * DD * DD, out_b + i * DD, x, x,
            NROWS, DD, DD);
        ln_kernel<<<NROWS, 256>>>(x, n2_s + i * DD, n2_b + i * DD, h);
        sgemm_kernel<1, 0><<<dim3(DF / 128, NROWS / 128), 256>>>(
            h, ff1_w + (size_t)i * DD * DF, ff1_b + i * DF, nullptr, ff,
            NROWS, DF, DD);
        sgemm_kernel<0, 1><<<dim3(DD / 128, NROWS / 128), 256>>>(
            ff, ff2_w + (size_t)i * DF * DD, ff2_b + i * DD, x, x,
            NROWS, DD, DF);
    }

    head_kernel<<<BB, 256>>>(x, hln_s, hln_b, cls_w, cls_b, out);
}

// round 4
// speedup vs baseline: 3.6972x; 3.6972x over previous
#include <cuda_runtime.h>
#include <cstdint>

// Problem constants
#define BB 8
#define SS 1024
#define DD 768
#define HH 12
#define LL 6
#define DF 3072
#define HD 64
#define TD 2304   // 3*D
#define NROWS (BB*SS)   // 8192

// ---------------- scratch (static device globals; no allocs allowed) -------------
__device__ float g_x[NROWS * DD];                 // residual stream
__device__ float g_h[NROWS * DD];                 // layernorm output
__device__ float g_qkv[NROWS * TD];               // qkv projection
__device__ float g_scores[(size_t)BB * HH * SS * SS];  // attention scores (403MB)
__device__ float g_att[NROWS * DD];               // attention output
__device__ float g_ff[NROWS * DF];                // ff1 output

// ---------------- helpers --------------------------------------------------------
__device__ __forceinline__ uint32_t f2tf(float f) {
    uint32_t u;
    asm("cvt.rna.tf32.f32 %0, %1;" : "=r"(u) : "f"(f));
    return u;
}

#define MMA_TF32(c, a, b)                                                        \
    asm volatile(                                                                \
        "mma.sync.aligned.m16n8k8.row.col.f32.tf32.tf32.f32 "                    \
        "{%0,%1,%2,%3},{%4,%5,%6,%7},{%8,%9},{%0,%1,%2,%3};"                     \
        : "+f"((c)[0]), "+f"((c)[1]), "+f"((c)[2]), "+f"((c)[3])                 \
        : "r"((a)[0]), "r"((a)[1]), "r"((a)[2]), "r"((a)[3]),                    \
          "r"((b)[0]), "r"((b)[1]))

// ---------------- embedding ------------------------------------------------------
__global__ void embed_kernel(const int* __restrict__ ids,
                             const float* __restrict__ tok,
                             const float* __restrict__ pos,
                             float* __restrict__ x) {
    int idx = blockIdx.x * blockDim.x + threadIdx.x;
    if (idx >= NROWS * DD) return;
    int bs = idx / DD;
    int d  = idx - bs * DD;
    int s  = bs & (SS - 1);
    x[idx] = (tok[(size_t)ids[bs] * DD + d] + pos[s * DD + d]) * 27.712812921102035f;
}

// ---------------- layernorm (block per row, 768 = 256*3) --------------------------
__global__ __launch_bounds__(256) void ln_kernel(const float* __restrict__ x,
                                                 const float* __restrict__ sc,
                                                 const float* __restrict__ bi,
                                                 float* __restrict__ out) {
    int row = blockIdx.x;
    int tid = threadIdx.x;
    const float* p = x + (size_t)row * DD;
    float v0 = p[tid], v1 = p[tid + 256], v2 = p[tid + 512];
    __shared__ float rs[256], rq[256];
    rs[tid] = v0 + v1 + v2;
    rq[tid] = v0 * v0 + v1 * v1 + v2 * v2;
    __syncthreads();
    for (int st = 128; st > 0; st >>= 1) {
        if (tid < st) { rs[tid] += rs[tid + st]; rq[tid] += rq[tid + st]; }
        __syncthreads();
    }
    float mean = rs[0] * (1.0f / DD);
    float var  = rq[0] * (1.0f / DD) - mean * mean;
    float inv  = rsqrtf(var + 1e-5f);
    float* o = out + (size_t)row * DD;
    o[tid]       = (v0 - mean) * inv * sc[tid]       + bi[tid];
    o[tid + 256] = (v1 - mean) * inv * sc[tid + 256] + bi[tid + 256];
    o[tid + 512] = (v2 - mean) * inv * sc[tid + 512] + bi[tid + 512];
}

// ---------------- tf32 tensor-core GEMM ------------------------------------------
// C[M,N] = A[M,K] @ B + epilogue.  BM=128, BK=32, 256 threads.
// BN = 128 or 64.  TRANSB: B stored [N,K] (row = n, stride ldb), else [K,N].
// Batched via blockIdx.z: ptr += (z/zdiv)*Out + (z%zdiv)*In.
template <int BN, bool TRANSB, bool BIAS, bool RELU, bool RES, bool MASK>
__global__ __launch_bounds__(256) void tgemm(
    const float* __restrict__ A, const float* __restrict__ B,
    const float* __restrict__ bias, const float* __restrict__ res,
    const int* __restrict__ mask, float* __restrict__ C,
    int K, int lda, int ldb, int ldc, int N,
    size_t aOut, size_t aIn, size_t bOut, size_t bIn,
    size_t cOut, size_t cIn, int zdiv)
{
    constexpr int BM = 128, BK = 32;
    constexpr int WGX = (BN == 128) ? 4 : 2;
    constexpr int WGY = 8 / WGX;
    constexpr int WM = BM / WGY;      // 64 or 32
    constexpr int WN = BN / WGX;      // 32
    constexpr int MT = WM / 16;       // 4 or 2
    constexpr int NT = WN / 8;        // 4
    constexpr int LA = BM * BK / 1024;   // 4 float4 per thread
    constexpr int LB = BK * BN / 1024;   // 4 or 2

    __shared__ uint32_t As[BM][BK + 4];   // [m][k] stride 36 words
    __shared__ uint32_t Bs[BK][BN + 8];   // [k][n]

    const int z = blockIdx.z;
    const float* Ab = A + (size_t)(z / zdiv) * aOut + (size_t)(z % zdiv) * aIn;
    const float* Bb = B + (size_t)(z / zdiv) * bOut + (size_t)(z % zdiv) * bIn;
    float*       Cb = C + (size_t)(z / zdiv) * cOut + (size_t)(z % zdiv) * cIn;

    const int tid = threadIdx.x;
    const int bm = blockIdx.y * BM;
    const int bn = blockIdx.x * BN;

    const int wid = tid >> 5, lane = tid & 31;
    const int gid = lane >> 2, tig = lane & 3;
    const int wn = (wid % WGX) * WN;
    const int wm = (wid / WGX) * WM;

    float acc[MT][NT][4];
#pragma unroll
    for (int mi = 0; mi < MT; mi++)
#pragma unroll
        for (int ni = 0; ni < NT; ni++)
#pragma unroll
            for (int q = 0; q < 4; q++) acc[mi][ni][q] = 0.f;

    // ---- initial global load (k-tile 0) into registers ----
    float4 pa[LA], pb[LB];
#pragma unroll
    for (int i = 0; i < LA; i++) {
        int f = i * 256 + tid;
        int r = f >> 3, kq = f & 7;
        pa[i] = *(const float4*)(Ab + (size_t)(bm + r) * lda + kq * 4);
    }
#pragma unroll
    for (int i = 0; i < LB; i++) {
        int f = i * 256 + tid;
        if (TRANSB) {
            int nr = f >> 3, kq = f & 7;
            pb[i] = *(const float4*)(Bb + (size_t)(bn + nr) * ldb + kq * 4);
        } else {
            int kr = f / (BN / 4), nq = f % (BN / 4);
            pb[i] = *(const float4*)(Bb + (size_t)kr * ldb + bn + nq * 4);
        }
    }

    const int KT = K / BK;
    for (int kt = 0; kt < KT; kt++) {
        // ---- store registers -> smem (tf32 convert) ----
#pragma unroll
        for (int i = 0; i < LA; i++) {
            int f = i * 256 + tid;
            int r = f >> 3, kq = f & 7;
            uint4 u = { f2tf(pa[i].x), f2tf(pa[i].y), f2tf(pa[i].z), f2tf(pa[i].w) };
            *(uint4*)(&As[r][kq * 4]) = u;
        }
#pragma unroll
        for (int i = 0; i < LB; i++) {
            int f = i * 256 + tid;
            if (TRANSB) {
                int nr = f >> 3, kq = f & 7;
                Bs[kq * 4 + 0][nr] = f2tf(pb[i].x);
                Bs[kq * 4 + 1][nr] = f2tf(pb[i].y);
                Bs[kq * 4 + 2][nr] = f2tf(pb[i].z);
                Bs[kq * 4 + 3][nr] = f2tf(pb[i].w);
            } else {
                int kr = f / (BN / 4), nq = f % (BN / 4);
                uint4 u = { f2tf(pb[i].x), f2tf(pb[i].y), f2tf(pb[i].z), f2tf(pb[i].w) };
                *(uint4*)(&Bs[kr][nq * 4]) = u;
            }
        }
        __syncthreads();

        // ---- prefetch next k-tile ----
        if (kt + 1 < KT) {
            int k0 = (kt + 1) * BK;
#pragma unroll
            for (int i = 0; i < LA; i++) {
                int f = i * 256 + tid;
                int r = f >> 3, kq = f & 7;
                pa[i] = *(const float4*)(Ab + (size_t)(bm + r) * lda + k0 + kq * 4);
            }
#pragma unroll
            for (int i = 0; i < LB; i++) {
                int f = i * 256 + tid;
                if (TRANSB) {
                    int nr = f >> 3, kq = f & 7;
                    pb[i] = *(const float4*)(Bb + (size_t)(bn + nr) * ldb + k0 + kq * 4);
                } else {
                    int kr = f / (BN / 4), nq = f % (BN / 4);
                    pb[i] = *(const float4*)(Bb + (size_t)(k0 + kr) * ldb + bn + nq * 4);
                }
            }
        }

        // ---- compute 4 k-steps of 8 ----
#pragma unroll
        for (int ks = 0; ks < BK; ks += 8) {
            uint32_t af[MT][4], bf[NT][2];
#pragma unroll
            for (int mi = 0; mi < MT; mi++) {
                int m = wm + mi * 16 + gid;
                af[mi][0] = As[m][ks + tig];
                af[mi][1] = As[m + 8][ks + tig];
                af[mi][2] = As[m][ks + tig + 4];
                af[mi][3] = As[m + 8][ks + tig + 4];
            }
#pragma unroll
            for (int ni = 0; ni < NT; ni++) {
                int n = wn + ni * 8 + gid;
                bf[ni][0] = Bs[ks + tig][n];
                bf[ni][1] = Bs[ks + tig + 4][n];
            }
#pragma unroll
            for (int mi = 0; mi < MT; mi++)
#pragma unroll
                for (int ni = 0; ni < NT; ni++)
                    MMA_TF32(acc[mi][ni], af[mi], bf[ni]);
        }
        __syncthreads();
    }

    // ---- epilogue ----
    const int* mrow = MASK ? (mask + (size_t)(z / zdiv) * N) : nullptr;
#pragma unroll
    for (int mi = 0; mi < MT; mi++) {
        int r0 = bm + wm + mi * 16 + gid;
#pragma unroll
        for (int ni = 0; ni < NT; ni++) {
            int c0 = bn + wn + ni * 8 + tig * 2;
#pragma unroll
            for (int q = 0; q < 4; q++) {
                int row = r0 + ((q >= 2) ? 8 : 0);
                int col = c0 + (q & 1);
                float v = acc[mi][ni][q];
                if (BIAS) v += bias[col];
                if (MASK) v = (mrow[col] == 1) ? -1e9f : v * 0.125f;
                if (RELU) v = fmaxf(v, 0.f);
                if (RES)  v += res[(size_t)row * ldc + col];
                Cb[(size_t)row * ldc + col] = v;
            }
        }
    }
}

// ---------------- softmax over last dim (row = 1024, block 256) -------------------
__global__ __launch_bounds__(256) void softmax_kernel(float* __restrict__ scores) {
    size_t row = blockIdx.x;
    float* p = scores + row * SS;
    int tid = threadIdx.x;
    float v[4];
#pragma unroll
    for (int i = 0; i < 4; i++) v[i] = p[tid + i * 256];
    float m = fmaxf(fmaxf(v[0], v[1]), fmaxf(v[2], v[3]));
    __shared__ float red[256];
    red[tid] = m;
    __syncthreads();
    for (int st = 128; st > 0; st >>= 1) {
        if (tid < st) red[tid] = fmaxf(red[tid], red[tid + st]);
        __syncthreads();
    }
    float M = red[0];
    __syncthreads();
    float e[4], s = 0.f;
#pragma unroll
    for (int i = 0; i < 4; i++) { e[i] = __expf(v[i] - M); s += e[i]; }
    red[tid] = s;
    __syncthreads();
    for (int st = 128; st > 0; st >>= 1) {
        if (tid < st) red[tid] += red[tid + st];
        __syncthreads();
    }
    float inv = 1.0f / red[0];
#pragma unroll
    for (int i = 0; i < 4; i++) p[tid + i * 256] = e[i] * inv;
}

// ---------------- final head: LN(x[:,0,:]) @ cls_w + cls_b ------------------------
__global__ __launch_bounds__(256) void head_kernel(const float* __restrict__ x,
                                                   const float* __restrict__ hs,
                                                   const float* __restrict__ hb,
                                                   const float* __restrict__ cw,
                                                   const float* __restrict__ cb,
                                                   float* __restrict__ out) {
    int b = blockIdx.x;
    int tid = threadIdx.x;
    const float* p = x + (size_t)b * SS * DD;   // s = 0 row
    float v0 = p[tid], v1 = p[tid + 256], v2 = p[tid + 512];
    __shared__ float rs[256], rq[256];
    rs[tid] = v0 + v1 + v2;
    rq[tid] = v0 * v0 + v1 * v1 + v2 * v2;
    __syncthreads();
    for (int st = 128; st > 0; st >>= 1) {
        if (tid < st) { rs[tid] += rs[tid + st]; rq[tid] += rq[tid + st]; }
        __syncthreads();
    }
    float mean = rs[0] * (1.0f / DD);
    float var  = rq[0] * (1.0f / DD) - mean * mean;
    float inv  = rsqrtf(var + 1e-5f);
    float p0 = (v0 - mean) * inv * hs[tid]       + hb[tid];
    float p1 = (v1 - mean) * inv * hs[tid + 256] + hb[tid + 256];
    float p2 = (v2 - mean) * inv * hs[tid + 512] + hb[tid + 512];
    float d0 = p0 * cw[2 * tid]     + p1 * cw[2 * (tid + 256)]     + p2 * cw[2 * (tid + 512)];
    float d1 = p0 * cw[2 * tid + 1] + p1 * cw[2 * (tid + 256) + 1] + p2 * cw[2 * (tid + 512) + 1];
    __syncthreads();
    rs[tid] = d0; rq[tid] = d1;
    __syncthreads();
    for (int st = 128; st > 0; st >>= 1) {
        if (tid < st) { rs[tid] += rs[tid + st]; rq[tid] += rq[tid + st]; }
        __syncthreads();
    }
    if (tid == 0) {
        out[2 * b]     = rs[0] + cb[0];
        out[2 * b + 1] = rq[0] + cb[1];
    }
}

// ---------------- host orchestration ---------------------------------------------
extern "C" void kernel_launch(void* const* d_in, const int* in_sizes, int n_in,
                              void* d_out, int out_size) {
    const int*   input_ids = (const int*)d_in[0];
    const int*   attn_mask = (const int*)d_in[1];
    const float* token_emb = (const float*)d_in[2];
    const float* pos_emb   = (const float*)d_in[3];
    const float* qkv_w     = (const float*)d_in[4];
    const float* qkv_b     = (const float*)d_in[5];
    const float* out_w     = (const float*)d_in[6];
    const float* out_b     = (const float*)d_in[7];
    const float* n1_s      = (const float*)d_in[8];
    const float* n1_b      = (const float*)d_in[9];
    const float* ff1_w     = (const float*)d_in[10];
    const float* ff1_b     = (const float*)d_in[11];
    const float* ff2_w     = (const float*)d_in[12];
    const float* ff2_b     = (const float*)d_in[13];
    const float* n2_s      = (const float*)d_in[14];
    const float* n2_b      = (const float*)d_in[15];
    const float* hln_s     = (const float*)d_in[16];
    const float* hln_b     = (const float*)d_in[17];
    const float* cls_w     = (const float*)d_in[18];
    const float* cls_b     = (const float*)d_in[19];
    float* out = (float*)d_out;

    float *x, *h, *qkv, *sc, *att, *ff;
    cudaGetSymbolAddress((void**)&x,   g_x);
    cudaGetSymbolAddress((void**)&h,   g_h);
    cudaGetSymbolAddress((void**)&qkv, g_qkv);
    cudaGetSymbolAddress((void**)&sc,  g_scores);
    cudaGetSymbolAddress((void**)&att, g_att);
    cudaGetSymbolAddress((void**)&ff,  g_ff);

    embed_kernel<<<(NROWS * DD + 255) / 256, 256>>>(input_ids, token_emb, pos_emb, x);

    const size_t SSTD = (size_t)SS * TD;
    const size_t SSSS = (size_t)SS * SS;
    const size_t SSDD = (size_t)SS * DD;

    for (int i = 0; i < LL; i++) {
        ln_kernel<<<NROWS, 256>>>(x, n1_s + i * DD, n1_b + i * DD, h);
        // QKV projection: [8192,768] @ [768,2304]
        tgemm<128, false, true, false, false, false><<<dim3(TD / 128, NROWS / 128, 1), 256>>>(
            h, qkv_w + (size_t)i * DD * TD, qkv_b + i * TD, nullptr, nullptr, qkv,
            DD, DD, TD, TD, TD, 0, 0, 0, 0, 0, 0, 1);
        // scores = Q @ K^T * scale, masked: per (b,h), [1024,64]@[64,1024]
        tgemm<128, true, false, false, false, true><<<dim3(SS / 128, SS / 128, BB * HH), 256>>>(
            qkv, qkv + 64, nullptr, nullptr, attn_mask, sc,
            HD, TD, TD, SS, SS,
            SSTD, 192, SSTD, 192, (size_t)HH * SSSS, SSSS, HH);
        softmax_kernel<<<BB * HH * SS, 256>>>(sc);
        // att = W @ V: per (b,h), [1024,1024]@[1024,64]
        tgemm<64, false, false, false, false, false><<<dim3(1, SS / 128, BB * HH), 256>>>(
            sc, qkv + 128, nullptr, nullptr, nullptr, att,
            SS, SS, TD, DD, 64,
            (size_t)HH * SSSS, SSSS, SSTD, 192, SSDD, 64, HH);
        // out projection + residual
        tgemm<128, false, true, false, true, false><<<dim3(DD / 128, NROWS / 128, 1), 256>>>(
            att, out_w + (size_t)i * DD * DD, out_b + i * DD, x, nullptr, x,
            DD, DD, DD, DD, DD, 0, 0, 0, 0, 0, 0, 1);
        ln_kernel<<<NROWS, 256>>>(x, n2_s + i * DD, n2_b + i * DD, h);
        // FF1 + relu
        tgemm<128, false, true, true, false, false><<<dim3(DF / 128, NROWS / 128, 1), 256>>>(
            h, ff1_w + (size_t)i * DD * DF, ff1_b + i * DF, nullptr, nullptr, ff,
            DD, DD, DF, DF, DF, 0, 0, 0, 0, 0, 0, 1);
        // FF2 + residual
        tgemm<128, false, true, false, true, false><<<dim3(DD / 128, NROWS / 128, 1), 256>>>(
            ff, ff2_w + (size_t)i * DF * DD, ff2_b + i * DD, x, nullptr, x,
            DF, DF, DD, DD, DD, 0, 0, 0, 0, 0, 0, 1);
    }

    head_kernel<<<BB, 256>>>(x, hln_s, hln_b, cls_w, cls_b, out);
}

// round 5
// speedup vs baseline: 4.3224x; 1.1691x over previous
#include <cuda_runtime.h>
#include <cstdint>

// Problem constants
#define BB 8
#define SS 1024
#define DD 768
#define HH 12
#define LL 6
#define DF 3072
#define HD 64
#define TD 2304   // 3*D
#define NROWS (BB*SS)   // 8192

// ---------------- scratch (static device globals; no allocs allowed) -------------
__device__ float g_x[NROWS * DD];                 // residual stream
__device__ float g_h[NROWS * DD];                 // layernorm output
__device__ float g_qkv[NROWS * TD];               // qkv projection
__device__ float g_att[NROWS * DD];               // attention output
__device__ float g_ff[NROWS * DF];                // ff1 output

// ---------------- helpers --------------------------------------------------------
__device__ __forceinline__ uint32_t f2tf(float f) {
    uint32_t u;
    asm("cvt.rna.tf32.f32 %0, %1;" : "=r"(u) : "f"(f));
    return u;
}

#define MMA_TF32(c, a, b)                                                        \
    asm volatile(                                                                \
        "mma.sync.aligned.m16n8k8.row.col.f32.tf32.tf32.f32 "                    \
        "{%0,%1,%2,%3},{%4,%5,%6,%7},{%8,%9},{%0,%1,%2,%3};"                     \
        : "+f"((c)[0]), "+f"((c)[1]), "+f"((c)[2]), "+f"((c)[3])                 \
        : "r"((a)[0]), "r"((a)[1]), "r"((a)[2]), "r"((a)[3]),                    \
          "r"((b)[0]), "r"((b)[1]))

// ---------------- embedding ------------------------------------------------------
__global__ void embed_kernel(const int* __restrict__ ids,
                             const float* __restrict__ tok,
                             const float* __restrict__ pos,
                             float* __restrict__ x) {
    int idx = blockIdx.x * blockDim.x + threadIdx.x;
    if (idx >= NROWS * DD) return;
    int bs = idx / DD;
    int d  = idx - bs * DD;
    int s  = bs & (SS - 1);
    x[idx] = (tok[(size_t)ids[bs] * DD + d] + pos[s * DD + d]) * 27.712812921102035f;
}

// ---------------- layernorm (block per row, 768 = 256*3) --------------------------
__global__ __launch_bounds__(256) void ln_kernel(const float* __restrict__ x,
                                                 const float* __restrict__ sc,
                                                 const float* __restrict__ bi,
                                                 float* __restrict__ out) {
    int row = blockIdx.x;
    int tid = threadIdx.x;
    const float* p = x + (size_t)row * DD;
    float v0 = p[tid], v1 = p[tid + 256], v2 = p[tid + 512];
    __shared__ float rs[256], rq[256];
    rs[tid] = v0 + v1 + v2;
    rq[tid] = v0 * v0 + v1 * v1 + v2 * v2;
    __syncthreads();
    for (int st = 128; st > 0; st >>= 1) {
        if (tid < st) { rs[tid] += rs[tid + st]; rq[tid] += rq[tid + st]; }
        __syncthreads();
    }
    float mean = rs[0] * (1.0f / DD);
    float var  = rq[0] * (1.0f / DD) - mean * mean;
    float inv  = rsqrtf(var + 1e-5f);
    float* o = out + (size_t)row * DD;
    o[tid]       = (v0 - mean) * inv * sc[tid]       + bi[tid];
    o[tid + 256] = (v1 - mean) * inv * sc[tid + 256] + bi[tid + 256];
    o[tid + 512] = (v2 - mean) * inv * sc[tid + 512] + bi[tid + 512];
}

// ---------------- tf32 tensor-core GEMM (dense projections) ----------------------
template <int BN, bool TRANSB, bool BIAS, bool RELU, bool RES, bool MASK>
__global__ __launch_bounds__(256) void tgemm(
    const float* __restrict__ A, const float* __restrict__ B,
    const float* __restrict__ bias, const float* __restrict__ res,
    const int* __restrict__ mask, float* __restrict__ C,
    int K, int lda, int ldb, int ldc, int N,
    size_t aOut, size_t aIn, size_t bOut, size_t bIn,
    size_t cOut, size_t cIn, int zdiv)
{
    constexpr int BM = 128, BK = 32;
    constexpr int WGX = (BN == 128) ? 4 : 2;
    constexpr int WGY = 8 / WGX;
    constexpr int WM = BM / WGY;
    constexpr int WN = BN / WGX;
    constexpr int MT = WM / 16;
    constexpr int NT = WN / 8;
    constexpr int LA = BM * BK / 1024;
    constexpr int LB = BK * BN / 1024;

    __shared__ uint32_t As[BM][BK + 4];
    __shared__ uint32_t Bs[BK][BN + 8];

    const int z = blockIdx.z;
    const float* Ab = A + (size_t)(z / zdiv) * aOut + (size_t)(z % zdiv) * aIn;
    const float* Bb = B + (size_t)(z / zdiv) * bOut + (size_t)(z % zdiv) * bIn;
    float*       Cb = C + (size_t)(z / zdiv) * cOut + (size_t)(z % zdiv) * cIn;

    const int tid = threadIdx.x;
    const int bm = blockIdx.y * BM;
    const int bn = blockIdx.x * BN;

    const int wid = tid >> 5, lane = tid & 31;
    const int gid = lane >> 2, tig = lane & 3;
    const int wn = (wid % WGX) * WN;
    const int wm = (wid / WGX) * WM;

    float acc[MT][NT][4];
#pragma unroll
    for (int mi = 0; mi < MT; mi++)
#pragma unroll
        for (int ni = 0; ni < NT; ni++)
#pragma unroll
            for (int q = 0; q < 4; q++) acc[mi][ni][q] = 0.f;

    float4 pa[LA], pb[LB];
#pragma unroll
    for (int i = 0; i < LA; i++) {
        int f = i * 256 + tid;
        int r = f >> 3, kq = f & 7;
        pa[i] = *(const float4*)(Ab + (size_t)(bm + r) * lda + kq * 4);
    }
#pragma unroll
    for (int i = 0; i < LB; i++) {
        int f = i * 256 + tid;
        if (TRANSB) {
            int nr = f >> 3, kq = f & 7;
            pb[i] = *(const float4*)(Bb + (size_t)(bn + nr) * ldb + kq * 4);
        } else {
            int kr = f / (BN / 4), nq = f % (BN / 4);
            pb[i] = *(const float4*)(Bb + (size_t)kr * ldb + bn + nq * 4);
        }
    }

    const int KT = K / BK;
    for (int kt = 0; kt < KT; kt++) {
#pragma unroll
        for (int i = 0; i < LA; i++) {
            int f = i * 256 + tid;
            int r = f >> 3, kq = f & 7;
            uint4 u = { f2tf(pa[i].x), f2tf(pa[i].y), f2tf(pa[i].z), f2tf(pa[i].w) };
            *(uint4*)(&As[r][kq * 4]) = u;
        }
#pragma unroll
        for (int i = 0; i < LB; i++) {
            int f = i * 256 + tid;
            if (TRANSB) {
                int nr = f >> 3, kq = f & 7;
                Bs[kq * 4 + 0][nr] = f2tf(pb[i].x);
                Bs[kq * 4 + 1][nr] = f2tf(pb[i].y);
                Bs[kq * 4 + 2][nr] = f2tf(pb[i].z);
                Bs[kq * 4 + 3][nr] = f2tf(pb[i].w);
            } else {
                int kr = f / (BN / 4), nq = f % (BN / 4);
                uint4 u = { f2tf(pb[i].x), f2tf(pb[i].y), f2tf(pb[i].z), f2tf(pb[i].w) };
                *(uint4*)(&Bs[kr][nq * 4]) = u;
            }
        }
        __syncthreads();

        if (kt + 1 < KT) {
            int k0 = (kt + 1) * BK;
#pragma unroll
            for (int i = 0; i < LA; i++) {
                int f = i * 256 + tid;
                int r = f >> 3, kq = f & 7;
                pa[i] = *(const float4*)(Ab + (size_t)(bm + r) * lda + k0 + kq * 4);
            }
#pragma unroll
            for (int i = 0; i < LB; i++) {
                int f = i * 256 + tid;
                if (TRANSB) {
                    int nr = f >> 3, kq = f & 7;
                    pb[i] = *(const float4*)(Bb + (size_t)(bn + nr) * ldb + k0 + kq * 4);
                } else {
                    int kr = f / (BN / 4), nq = f % (BN / 4);
                    pb[i] = *(const float4*)(Bb + (size_t)(k0 + kr) * ldb + bn + nq * 4);
                }
            }
        }

#pragma unroll
        for (int ks = 0; ks < BK; ks += 8) {
            uint32_t af[MT][4], bf[NT][2];
#pragma unroll
            for (int mi = 0; mi < MT; mi++) {
                int m = wm + mi * 16 + gid;
                af[mi][0] = As[m][ks + tig];
                af[mi][1] = As[m + 8][ks + tig];
                af[mi][2] = As[m][ks + tig + 4];
                af[mi][3] = As[m + 8][ks + tig + 4];
            }
#pragma unroll
            for (int ni = 0; ni < NT; ni++) {
                int n = wn + ni * 8 + gid;
                bf[ni][0] = Bs[ks + tig][n];
                bf[ni][1] = Bs[ks + tig + 4][n];
            }
#pragma unroll
            for (int mi = 0; mi < MT; mi++)
#pragma unroll
                for (int ni = 0; ni < NT; ni++)
                    MMA_TF32(acc[mi][ni], af[mi], bf[ni]);
        }
        __syncthreads();
    }

    const int* mrow = MASK ? (mask + (size_t)(z / zdiv) * N) : nullptr;
#pragma unroll
    for (int mi = 0; mi < MT; mi++) {
        int r0 = bm + wm + mi * 16 + gid;
#pragma unroll
        for (int ni = 0; ni < NT; ni++) {
            int c0 = bn + wn + ni * 8 + tig * 2;
#pragma unroll
            for (int q = 0; q < 4; q++) {
                int row = r0 + ((q >= 2) ? 8 : 0);
                int col = c0 + (q & 1);
                float v = acc[mi][ni][q];
                if (BIAS) v += bias[col];
                if (MASK) v = (mrow[col] == 1) ? -1e9f : v * 0.125f;
                if (RELU) v = fmaxf(v, 0.f);
                if (RES)  v += res[(size_t)row * ldc + col];
                Cb[(size_t)row * ldc + col] = v;
            }
        }
    }
}

// ---------------- fused flash attention ------------------------------------------
// One CTA per (128 q-rows, b, h). Online softmax, score tensor never hits DRAM.
// 8 warps x 16 rows. Q frags in regs; K/V 64-wide tiles with register prefetch.
#define FA_SMEM ((128 * 68 + 2 * 64 * 72 + 64) * 4)

__global__ __launch_bounds__(256) void fattn_kernel(
    const float* __restrict__ qkv, const int* __restrict__ mask,
    float* __restrict__ att)
{
    extern __shared__ uint32_t dsm[];
    uint32_t (*Ps)[68] = (uint32_t(*)[68])dsm;                     // P (and Q staging)
    uint32_t (*Ks)[72] = (uint32_t(*)[72])(dsm + 128 * 68);        // K tile [t][hd]
    uint32_t (*Vs)[72] = (uint32_t(*)[72])(dsm + 128 * 68 + 64 * 72);  // V tile [t][hd]
    int* msk = (int*)(dsm + 128 * 68 + 2 * 64 * 72);

    const int bh = blockIdx.y, b = bh / HH, h = bh % HH;
    const int s0 = blockIdx.x * 128;
    const int tid = threadIdx.x, wid = tid >> 5, lane = tid & 31;
    const int gid = lane >> 2, tig = lane & 3;

    const float* Qg = qkv + (size_t)(b * SS + s0) * TD + h * 192;
    const float* Kg = qkv + (size_t)b * SS * TD + h * 192 + 64;
    const float* Vg = Kg + 64;
    const int* mrow = mask + b * SS;

    // ---- stage Q (128x64) via smem into A-fragments ----
    {
        int r = tid >> 1;
        int c0 = (tid & 1) * 8;
#pragma unroll
        for (int i = 0; i < 8; i++) {
            float4 v = *(const float4*)(Qg + (size_t)r * TD + (c0 + i) * 4);
            uint4 u = { f2tf(v.x), f2tf(v.y), f2tf(v.z), f2tf(v.w) };
            *(uint4*)(&Ps[r][(c0 + i) * 4]) = u;
        }
    }
    __syncthreads();
    uint32_t qf[8][4];
    {
        int m = wid * 16 + gid;
#pragma unroll
        for (int kt = 0; kt < 8; kt++) {
            qf[kt][0] = Ps[m][kt * 8 + tig];
            qf[kt][1] = Ps[m + 8][kt * 8 + tig];
            qf[kt][2] = Ps[m][kt * 8 + tig + 4];
            qf[kt][3] = Ps[m + 8][kt * 8 + tig + 4];
        }
    }

    float of[8][4];
#pragma unroll
    for (int ni = 0; ni < 8; ni++)
#pragma unroll
        for (int q = 0; q < 4; q++) of[ni][q] = 0.f;
    float mrun[2] = { -INFINITY, -INFINITY };
    float lrun[2] = { 0.f, 0.f };

    // K/V tile prefetch mapping: 64 rows x 16 float4; 4 threads/row, 4 float4 each
    const int pr = tid >> 2;
    const int pc = (tid & 3) * 4;
    float4 pk[4], pv[4];
    int pm;
    {
        const float* kp = Kg + (size_t)pr * TD;
        const float* vp = Vg + (size_t)pr * TD;
#pragma unroll
        for (int i = 0; i < 4; i++) {
            pk[i] = *(const float4*)(kp + (pc + i) * 4);
            pv[i] = *(const float4*)(vp + (pc + i) * 4);
        }
        pm = (tid < 64) ? mrow[tid] : 0;
    }

    for (int tc = 0; tc < SS / 64; tc++) {
        __syncthreads();   // prior iteration finished reading Ks/Vs (and Q frags loaded)
#pragma unroll
        for (int i = 0; i < 4; i++) {
            uint4 uk = { f2tf(pk[i].x), f2tf(pk[i].y), f2tf(pk[i].z), f2tf(pk[i].w) };
            *(uint4*)(&Ks[pr][(pc + i) * 4]) = uk;
            uint4 uv = { f2tf(pv[i].x), f2tf(pv[i].y), f2tf(pv[i].z), f2tf(pv[i].w) };
            *(uint4*)(&Vs[pr][(pc + i) * 4]) = uv;
        }
        if (tid < 64) msk[tid] = pm;
        __syncthreads();

        if (tc + 1 < SS / 64) {
            int t0n = (tc + 1) * 64;
            const float* kp = Kg + (size_t)(t0n + pr) * TD;
            const float* vp = Vg + (size_t)(t0n + pr) * TD;
#pragma unroll
            for (int i = 0; i < 4; i++) {
                pk[i] = *(const float4*)(kp + (pc + i) * 4);
                pv[i] = *(const float4*)(vp + (pc + i) * 4);
            }
            pm = (tid < 64) ? mrow[t0n + tid] : 0;
        }

        // ---- S = Q @ K^T (warp rows x 64 cols) ----
        float sf[8][4];
#pragma unroll
        for (int ni = 0; ni < 8; ni++)
#pragma unroll
            for (int q = 0; q < 4; q++) sf[ni][q] = 0.f;
#pragma unroll
        for (int kt = 0; kt < 8; kt++) {
#pragma unroll
            for (int ni = 0; ni < 8; ni++) {
                uint32_t bf[2];
                bf[0] = Ks[ni * 8 + gid][kt * 8 + tig];
                bf[1] = Ks[ni * 8 + gid][kt * 8 + tig + 4];
                MMA_TF32(sf[ni], qf[kt], bf);
            }
        }

        // ---- mask + scale + online softmax ----
        float mnew0 = mrun[0], mnew1 = mrun[1];
#pragma unroll
        for (int ni = 0; ni < 8; ni++) {
            int c = ni * 8 + 2 * tig;
            bool m0 = msk[c] == 1, m1 = msk[c + 1] == 1;
            sf[ni][0] = m0 ? -1e9f : sf[ni][0] * 0.125f;
            sf[ni][1] = m1 ? -1e9f : sf[ni][1] * 0.125f;
            sf[ni][2] = m0 ? -1e9f : sf[ni][2] * 0.125f;
            sf[ni][3] = m1 ? -1e9f : sf[ni][3] * 0.125f;
            mnew0 = fmaxf(mnew0, fmaxf(sf[ni][0], sf[ni][1]));
            mnew1 = fmaxf(mnew1, fmaxf(sf[ni][2], sf[ni][3]));
        }
        mnew0 = fmaxf(mnew0, __shfl_xor_sync(0xffffffffu, mnew0, 1));
        mnew0 = fmaxf(mnew0, __shfl_xor_sync(0xffffffffu, mnew0, 2));
        mnew1 = fmaxf(mnew1, __shfl_xor_sync(0xffffffffu, mnew1, 1));
        mnew1 = fmaxf(mnew1, __shfl_xor_sync(0xffffffffu, mnew1, 2));
        float alpha0 = __expf(mrun[0] - mnew0);
        float alpha1 = __expf(mrun[1] - mnew1);
        mrun[0] = mnew0; mrun[1] = mnew1;

        float rs0 = 0.f, rs1 = 0.f;
#pragma unroll
        for (int ni = 0; ni < 8; ni++) {
            sf[ni][0] = __expf(sf[ni][0] - mnew0);
            sf[ni][1] = __expf(sf[ni][1] - mnew0);
            sf[ni][2] = __expf(sf[ni][2] - mnew1);
            sf[ni][3] = __expf(sf[ni][3] - mnew1);
            rs0 += sf[ni][0] + sf[ni][1];
            rs1 += sf[ni][2] + sf[ni][3];
        }
        rs0 += __shfl_xor_sync(0xffffffffu, rs0, 1);
        rs0 += __shfl_xor_sync(0xffffffffu, rs0, 2);
        rs1 += __shfl_xor_sync(0xffffffffu, rs1, 1);
        rs1 += __shfl_xor_sync(0xffffffffu, rs1, 2);
        lrun[0] = lrun[0] * alpha0 + rs0;
        lrun[1] = lrun[1] * alpha1 + rs1;
#pragma unroll
        for (int ni = 0; ni < 8; ni++) {
            of[ni][0] *= alpha0; of[ni][1] *= alpha0;
            of[ni][2] *= alpha1; of[ni][3] *= alpha1;
        }

        // ---- write P to smem (own rows only; no inter-warp dependency) ----
        {
            int r0 = wid * 16 + gid;
#pragma unroll
            for (int ni = 0; ni < 8; ni++) {
                int c = ni * 8 + 2 * tig;
                uint2 u0 = { f2tf(sf[ni][0]), f2tf(sf[ni][1]) };
                *(uint2*)(&Ps[r0][c]) = u0;
                uint2 u1 = { f2tf(sf[ni][2]), f2tf(sf[ni][3]) };
                *(uint2*)(&Ps[r0 + 8][c]) = u1;
            }
        }

        // ---- O += P @ V (reads only this warp's P rows -> no barrier needed) ----
        {
            int m = wid * 16 + gid;
#pragma unroll
            for (int kt = 0; kt < 8; kt++) {
                uint32_t a[4];
                a[0] = Ps[m][kt * 8 + tig];
                a[1] = Ps[m + 8][kt * 8 + tig];
                a[2] = Ps[m][kt * 8 + tig + 4];
                a[3] = Ps[m + 8][kt * 8 + tig + 4];
#pragma unroll
                for (int ni = 0; ni < 8; ni++) {
                    uint32_t bf[2];
                    bf[0] = Vs[kt * 8 + tig][ni * 8 + gid];
                    bf[1] = Vs[kt * 8 + tig + 4][ni * 8 + gid];
                    MMA_TF32(of[ni], a, bf);
                }
            }
        }
    }

    // ---- epilogue: O /= l, write to att ----
    float inv0 = 1.f / lrun[0];
    float inv1 = 1.f / lrun[1];
    int r0 = s0 + wid * 16 + gid;
#pragma unroll
    for (int ni = 0; ni < 8; ni++) {
        int c = h * 64 + ni * 8 + 2 * tig;
        float2 v0 = { of[ni][0] * inv0, of[ni][1] * inv0 };
        *(float2*)(att + (size_t)(b * SS + r0) * DD + c) = v0;
        float2 v1 = { of[ni][2] * inv1, of[ni][3] * inv1 };
        *(float2*)(att + (size_t)(b * SS + r0 + 8) * DD + c) = v1;
    }
}

// ---------------- final head: LN(x[:,0,:]) @ cls_w + cls_b ------------------------
__global__ __launch_bounds__(256) void head_kernel(const float* __restrict__ x,
                                                   const float* __restrict__ hs,
                                                   const float* __restrict__ hb,
                                                   const float* __restrict__ cw,
                                                   const float* __restrict__ cb,
                                                   float* __restrict__ out) {
    int b = blockIdx.x;
    int tid = threadIdx.x;
    const float* p = x + (size_t)b * SS * DD;   // s = 0 row
    float v0 = p[tid], v1 = p[tid + 256], v2 = p[tid + 512];
    __shared__ float rs[256], rq[256];
    rs[tid] = v0 + v1 + v2;
    rq[tid] = v0 * v0 + v1 * v1 + v2 * v2;
    __syncthreads();
    for (int st = 128; st > 0; st >>= 1) {
        if (tid < st) { rs[tid] += rs[tid + st]; rq[tid] += rq[tid + st]; }
        __syncthreads();
    }
    float mean = rs[0] * (1.0f / DD);
    float var  = rq[0] * (1.0f / DD) - mean * mean;
    float inv  = rsqrtf(var + 1e-5f);
    float p0 = (v0 - mean) * inv * hs[tid]       + hb[tid];
    float p1 = (v1 - mean) * inv * hs[tid + 256] + hb[tid + 256];
    float p2 = (v2 - mean) * inv * hs[tid + 512] + hb[tid + 512];
    float d0 = p0 * cw[2 * tid]     + p1 * cw[2 * (tid + 256)]     + p2 * cw[2 * (tid + 512)];
    float d1 = p0 * cw[2 * tid + 1] + p1 * cw[2 * (tid + 256) + 1] + p2 * cw[2 * (tid + 512) + 1];
    __syncthreads();
    rs[tid] = d0; rq[tid] = d1;
    __syncthreads();
    for (int st = 128; st > 0; st >>= 1) {
        if (tid < st) { rs[tid] += rs[tid + st]; rq[tid] += rq[tid + st]; }
        __syncthreads();
    }
    if (tid == 0) {
        out[2 * b]     = rs[0] + cb[0];
        out[2 * b + 1] = rq[0] + cb[1];
    }
}

// ---------------- host orchestration ---------------------------------------------
extern "C" void kernel_launch(void* const* d_in, const int* in_sizes, int n_in,
                              void* d_out, int out_size) {
    const int*   input_ids = (const int*)d_in[0];
    const int*   attn_mask = (const int*)d_in[1];
    const float* token_emb = (const float*)d_in[2];
    const float* pos_emb   = (const float*)d_in[3];
    const float* qkv_w     = (const float*)d_in[4];
    const float* qkv_b     = (const float*)d_in[5];
    const float* out_w     = (const float*)d_in[6];
    const float* out_b     = (const float*)d_in[7];
    const float* n1_s      = (const float*)d_in[8];
    const float* n1_b      = (const float*)d_in[9];
    const float* ff1_w     = (const float*)d_in[10];
    const float* ff1_b     = (const float*)d_in[11];
    const float* ff2_w     = (const float*)d_in[12];
    const float* ff2_b     = (const float*)d_in[13];
    const float* n2_s      = (const float*)d_in[14];
    const float* n2_b      = (const float*)d_in[15];
    const float* hln_s     = (const float*)d_in[16];
    const float* hln_b     = (const float*)d_in[17];
    const float* cls_w     = (const float*)d_in[18];
    const float* cls_b     = (const float*)d_in[19];
    float* out = (float*)d_out;

    float *x, *h, *qkv, *att, *ff;
    cudaGetSymbolAddress((void**)&x,   g_x);
    cudaGetSymbolAddress((void**)&h,   g_h);
    cudaGetSymbolAddress((void**)&qkv, g_qkv);
    cudaGetSymbolAddress((void**)&att, g_att);
    cudaGetSymbolAddress((void**)&ff,  g_ff);

    static bool attr_set = false;
    if (!attr_set) {
        cudaFuncSetAttribute(fattn_kernel,
                             cudaFuncAttributeMaxDynamicSharedMemorySize, FA_SMEM);
        attr_set = true;
    }

    embed_kernel<<<(NROWS * DD + 255) / 256, 256>>>(input_ids, token_emb, pos_emb, x);

    for (int i = 0; i < LL; i++) {
        ln_kernel<<<NROWS, 256>>>(x, n1_s + i * DD, n1_b + i * DD, h);
        // QKV projection: [8192,768] @ [768,2304]
        tgemm<128, false, true, false, false, false><<<dim3(TD / 128, NROWS / 128, 1), 256>>>(
            h, qkv_w + (size_t)i * DD * TD, qkv_b + i * TD, nullptr, nullptr, qkv,
            DD, DD, TD, TD, TD, 0, 0, 0, 0, 0, 0, 1);
        // fused attention: scores + softmax + P@V, no DRAM score tensor
        fattn_kernel<<<dim3(SS / 128, BB * HH), 256, FA_SMEM>>>(qkv, attn_mask, att);
        // out projection + residual
        tgemm<128, false, true, false, true, false><<<dim3(DD / 128, NROWS / 128, 1), 256>>>(
            att, out_w + (size_t)i * DD * DD, out_b + i * DD, x, nullptr, x,
            DD, DD, DD, DD, DD, 0, 0, 0, 0, 0, 0, 1);
        ln_kernel<<<NROWS, 256>>>(x, n2_s + i * DD, n2_b + i * DD, h);
        // FF1 + relu
        tgemm<128, false, true, true, false, false><<<dim3(DF / 128, NROWS / 128, 1), 256>>>(
            h, ff1_w + (size_t)i * DD * DF, ff1_b + i * DF, nullptr, nullptr, ff,
            DD, DD, DF, DF, DF, 0, 0, 0, 0, 0, 0, 1);
        // FF2 + residual
        tgemm<128, false, true, false, true, false><<<dim3(DD / 128, NROWS / 128, 1), 256>>>(
            ff, ff2_w + (size_t)i * DF * DD, ff2_b + i * DD, x, nullptr, x,
            DF, DF, DD, DD, DD, 0, 0, 0, 0, 0, 0, 1);
    }

    head_kernel<<<BB, 256>>>(x, hln_s, hln_b, cls_w, cls_b, out);
}

// round 6
// speedup vs baseline: 5.3012x; 1.2264x over previous
#include <cuda_runtime.h>
#include <cstdint>

// Problem constants
#define BB 8
#define SS 1024
#define DD 768
#define HH 12
#define LL 6
#define DF 3072
#define HD 64
#define TD 2304   // 3*D
#define NROWS (BB*SS)   // 8192

// ---------------- scratch (static device globals; no allocs allowed) -------------
__device__ float g_x[NROWS * DD];                 // residual stream
__device__ float g_h[NROWS * DD];                 // layernorm output
__device__ float g_qkv[NROWS * TD];               // qkv projection
__device__ float g_att[NROWS * DD];               // attention output
__device__ float g_ff[NROWS * DF];                // ff1 output

// ---------------- helpers --------------------------------------------------------
__device__ __forceinline__ uint32_t f2tf(float f) {
    uint32_t u;
    asm("cvt.rna.tf32.f32 %0, %1;" : "=r"(u) : "f"(f));
    return u;
}

#define MMA_TF32(c, a, b)                                                        \
    asm volatile(                                                                \
        "mma.sync.aligned.m16n8k8.row.col.f32.tf32.tf32.f32 "                    \
        "{%0,%1,%2,%3},{%4,%5,%6,%7},{%8,%9},{%0,%1,%2,%3};"                     \
        : "+f"((c)[0]), "+f"((c)[1]), "+f"((c)[2]), "+f"((c)[3])                 \
        : "r"((a)[0]), "r"((a)[1]), "r"((a)[2]), "r"((a)[3]),                    \
          "r"((b)[0]), "r"((b)[1]))

#define CP_ASYNC16(dst, src)                                                     \
    asm volatile("cp.async.cg.shared.global [%0], [%1], 16;" :: "r"(dst), "l"(src))
#define CP_COMMIT() asm volatile("cp.async.commit_group;")
#define CP_WAIT(n)  asm volatile("cp.async.wait_group %0;" :: "n"(n))

// ---------------- embedding ------------------------------------------------------
__global__ void embed_kernel(const int* __restrict__ ids,
                             const float* __restrict__ tok,
                             const float* __restrict__ pos,
                             float* __restrict__ x) {
    int idx = blockIdx.x * blockDim.x + threadIdx.x;
    if (idx >= NROWS * DD) return;
    int bs = idx / DD;
    int d  = idx - bs * DD;
    int s  = bs & (SS - 1);
    x[idx] = (tok[(size_t)ids[bs] * DD + d] + pos[s * DD + d]) * 27.712812921102035f;
}

// ---------------- layernorm (block per row, 768 = 256*3) --------------------------
__global__ __launch_bounds__(256) void ln_kernel(const float* __restrict__ x,
                                                 const float* __restrict__ sc,
                                                 const float* __restrict__ bi,
                                                 float* __restrict__ out) {
    int row = blockIdx.x;
    int tid = threadIdx.x;
    const float* p = x + (size_t)row * DD;
    float v0 = p[tid], v1 = p[tid + 256], v2 = p[tid + 512];
    __shared__ float rs[256], rq[256];
    rs[tid] = v0 + v1 + v2;
    rq[tid] = v0 * v0 + v1 * v1 + v2 * v2;
    __syncthreads();
    for (int st = 128; st > 0; st >>= 1) {
        if (tid < st) { rs[tid] += rs[tid + st]; rq[tid] += rq[tid + st]; }
        __syncthreads();
    }
    float mean = rs[0] * (1.0f / DD);
    float var  = rq[0] * (1.0f / DD) - mean * mean;
    float inv  = rsqrtf(var + 1e-5f);
    float* o = out + (size_t)row * DD;
    o[tid]       = (v0 - mean) * inv * sc[tid]       + bi[tid];
    o[tid + 256] = (v1 - mean) * inv * sc[tid + 256] + bi[tid + 256];
    o[tid + 512] = (v2 - mean) * inv * sc[tid + 512] + bi[tid + 512];
}

// ---------------- tf32 GEMM v2: cp.async double-buffered, 2 CTAs/SM --------------
// C[M,N] = A[M,K] @ B[K,N] + bias (+relu)(+res).  BM=128, BN=128, BK=32.
// smem holds raw fp32; tf32 convert happens at fragment load.
#define TG_ASTR 36
#define TG_BSTR 136
#define TG_ABUF (128 * TG_ASTR)            // 4608 words
#define TG_BBUF (32 * TG_BSTR)             // 4352 words
#define TG_BUF  (TG_ABUF + TG_BBUF)        // 8960 words
#define TG_SMEM (2 * TG_BUF * 4)           // 71680 bytes

template <bool RELU, bool RES>
__global__ __launch_bounds__(256, 2) void tgemm2(
    const float* __restrict__ A, const float* __restrict__ B,
    const float* __restrict__ bias, const float* __restrict__ res,
    float* __restrict__ C, int K, int N)
{
    constexpr int BK = 32;
    extern __shared__ float sm[];
    const uint32_t sbase = (uint32_t)__cvta_generic_to_shared(sm);

    const int tid = threadIdx.x;
    const int bm = blockIdx.y * 128;
    const int bn = blockIdx.x * 128;
    const int wid = tid >> 5, lane = tid & 31;
    const int gid = lane >> 2, tig = lane & 3;
    const int wn = (wid & 3) * 32;
    const int wm = (wid >> 2) * 64;

    const float* Ab = A + (size_t)bm * K;

    float acc[4][4][4];
#pragma unroll
    for (int mi = 0; mi < 4; mi++)
#pragma unroll
        for (int ni = 0; ni < 4; ni++)
#pragma unroll
            for (int q = 0; q < 4; q++) acc[mi][ni][q] = 0.f;

    auto issue = [&](int kt, int p) {
        int k0 = kt * BK;
#pragma unroll
        for (int i = 0; i < 4; i++) {
            int f = i * 256 + tid;
            int r = f >> 3, kq = f & 7;
            uint32_t d = sbase + (uint32_t)(p * TG_BUF + r * TG_ASTR + kq * 4) * 4;
            CP_ASYNC16(d, Ab + (size_t)r * K + k0 + kq * 4);
        }
#pragma unroll
        for (int i = 0; i < 4; i++) {
            int f = i * 256 + tid;
            int kr = f >> 5, nq = f & 31;
            uint32_t d = sbase + (uint32_t)(p * TG_BUF + TG_ABUF + kr * TG_BSTR + nq * 4) * 4;
            CP_ASYNC16(d, B + (size_t)(k0 + kr) * N + bn + nq * 4);
        }
        CP_COMMIT();
    };

    issue(0, 0);

    const int KT = K / BK;
    for (int kt = 0; kt < KT; kt++) {
        const int p = kt & 1;
        if (kt + 1 < KT) { issue(kt + 1, p ^ 1); CP_WAIT(1); }
        else             { CP_WAIT(0); }
        __syncthreads();

        const float* As = sm + p * TG_BUF;
        const float* Bs = sm + p * TG_BUF + TG_ABUF;
#pragma unroll
        for (int ks = 0; ks < BK; ks += 8) {
            uint32_t af[4][4], bf[4][2];
#pragma unroll
            for (int mi = 0; mi < 4; mi++) {
                int m = wm + mi * 16 + gid;
                af[mi][0] = f2tf(As[m * TG_ASTR + ks + tig]);
                af[mi][1] = f2tf(As[(m + 8) * TG_ASTR + ks + tig]);
                af[mi][2] = f2tf(As[m * TG_ASTR + ks + tig + 4]);
                af[mi][3] = f2tf(As[(m + 8) * TG_ASTR + ks + tig + 4]);
            }
#pragma unroll
            for (int ni = 0; ni < 4; ni++) {
                int n = wn + ni * 8 + gid;
                bf[ni][0] = f2tf(Bs[(ks + tig) * TG_BSTR + n]);
                bf[ni][1] = f2tf(Bs[(ks + tig + 4) * TG_BSTR + n]);
            }
#pragma unroll
            for (int mi = 0; mi < 4; mi++)
#pragma unroll
                for (int ni = 0; ni < 4; ni++)
                    MMA_TF32(acc[mi][ni], af[mi], bf[ni]);
        }
        __syncthreads();
    }

    // ---- epilogue ----
#pragma unroll
    for (int mi = 0; mi < 4; mi++) {
        int r0 = bm + wm + mi * 16 + gid;
#pragma unroll
        for (int ni = 0; ni < 4; ni++) {
            int c = bn + wn + ni * 8 + tig * 2;
            float b0 = bias[c], b1 = bias[c + 1];
            float v0 = acc[mi][ni][0] + b0;
            float v1 = acc[mi][ni][1] + b1;
            float v2 = acc[mi][ni][2] + b0;
            float v3 = acc[mi][ni][3] + b1;
            if (RELU) {
                v0 = fmaxf(v0, 0.f); v1 = fmaxf(v1, 0.f);
                v2 = fmaxf(v2, 0.f); v3 = fmaxf(v3, 0.f);
            }
            if (RES) {
                const float* rp0 = res + (size_t)r0 * N + c;
                const float* rp1 = res + (size_t)(r0 + 8) * N + c;
                v0 += rp0[0]; v1 += rp0[1];
                v2 += rp1[0]; v3 += rp1[1];
            }
            float2 w0 = { v0, v1 };
            float2 w1 = { v2, v3 };
            *(float2*)(C + (size_t)r0 * N + c) = w0;
            *(float2*)(C + (size_t)(r0 + 8) * N + c) = w1;
        }
    }
}

// ---------------- fused flash attention v2 ---------------------------------------
// One CTA per (128 q-rows, b, h). cp.async double-buffered K/V, mask preloaded,
// 2 CTAs/SM target. Smem words: Ps 8704 | KV 2x(4608+4608) | msk 1024.
#define FA_PS    0
#define FA_KV    8704
#define FA_KVBUF 9216                       // one K+V pair (words)
#define FA_MSK   (FA_KV + 2 * FA_KVBUF)     // 27136
#define FA_WORDS (FA_MSK + 1024)            // 28160
#define FA_SMEM  (FA_WORDS * 4)             // 112640 bytes

__global__ __launch_bounds__(256, 2) void fattn_kernel(
    const float* __restrict__ qkv, const int* __restrict__ mask,
    float* __restrict__ att)
{
    extern __shared__ float sm[];
    const uint32_t sbase = (uint32_t)__cvta_generic_to_shared(sm);
    uint32_t (*Ps)[68] = (uint32_t(*)[68])sm;
    int* msk = (int*)(sm + FA_MSK);

    const int bh = blockIdx.y, b = bh / HH, h = bh % HH;
    const int s0 = blockIdx.x * 128;
    const int tid = threadIdx.x, wid = tid >> 5, lane = tid & 31;
    const int gid = lane >> 2, tig = lane & 3;

    const float* Qg = qkv + (size_t)(b * SS + s0) * TD + h * 192;
    const float* Kg = qkv + (size_t)b * SS * TD + h * 192 + 64;
    const float* Vg = Kg + 64;

    // K/V cp.async mapping: 64 rows x 16 float4; 4 threads/row, 4 float4 each
    const int pr = tid >> 2;
    const int pc = (tid & 3) * 4;

    auto issueKV = [&](int tc, int p) {
        int t0 = tc * 64;
        const float* kp = Kg + (size_t)(t0 + pr) * TD;
        const float* vp = Vg + (size_t)(t0 + pr) * TD;
        uint32_t kd = sbase + (uint32_t)(FA_KV + p * FA_KVBUF + pr * 72) * 4;
        uint32_t vd = kd + 4608 * 4;
#pragma unroll
        for (int i = 0; i < 4; i++) {
            CP_ASYNC16(kd + (pc + i) * 16, kp + (pc + i) * 4);
            CP_ASYNC16(vd + (pc + i) * 16, vp + (pc + i) * 4);
        }
        CP_COMMIT();
    };

    issueKV(0, 0);

    // ---- preload mask row (1024 ints) ----
    ((int4*)msk)[tid] = ((const int4*)(mask + b * SS))[tid];

    // ---- stage Q (128x64) via Ps into A-fragments ----
    {
        int r = tid >> 1;
        int c0 = (tid & 1) * 8;
#pragma unroll
        for (int i = 0; i < 8; i++) {
            float4 v = *(const float4*)(Qg + (size_t)r * TD + (c0 + i) * 4);
            uint4 u = { f2tf(v.x), f2tf(v.y), f2tf(v.z), f2tf(v.w) };
            *(uint4*)(&Ps[r][(c0 + i) * 4]) = u;
        }
    }
    __syncthreads();
    uint32_t qf[8][4];
    {
        int m = wid * 16 + gid;
#pragma unroll
        for (int kt = 0; kt < 8; kt++) {
            qf[kt][0] = Ps[m][kt * 8 + tig];
            qf[kt][1] = Ps[m + 8][kt * 8 + tig];
            qf[kt][2] = Ps[m][kt * 8 + tig + 4];
            qf[kt][3] = Ps[m + 8][kt * 8 + tig + 4];
        }
    }
    __syncthreads();   // Q frags loaded before Ps reused for P

    float of[8][4];
#pragma unroll
    for (int ni = 0; ni < 8; ni++)
#pragma unroll
        for (int q = 0; q < 4; q++) of[ni][q] = 0.f;
    float mrun0 = -INFINITY, mrun1 = -INFINITY;
    float lrun0 = 0.f, lrun1 = 0.f;

    for (int tc = 0; tc < SS / 64; tc++) {
        const int p = tc & 1;
        if (tc + 1 < SS / 64) { issueKV(tc + 1, p ^ 1); CP_WAIT(1); }
        else                  { CP_WAIT(0); }
        __syncthreads();

        const float (*Kf)[72] = (const float(*)[72])(sm + FA_KV + p * FA_KVBUF);
        const float (*Vf)[72] = (const float(*)[72])(sm + FA_KV + p * FA_KVBUF + 4608);
        const int* mt = msk + tc * 64;

        // ---- S = Q @ K^T ----
        float sf[8][4];
#pragma unroll
        for (int ni = 0; ni < 8; ni++)
#pragma unroll
            for (int q = 0; q < 4; q++) sf[ni][q] = 0.f;
#pragma unroll
        for (int kt = 0; kt < 8; kt++) {
#pragma unroll
            for (int ni = 0; ni < 8; ni++) {
                uint32_t bf[2];
                bf[0] = f2tf(Kf[ni * 8 + gid][kt * 8 + tig]);
                bf[1] = f2tf(Kf[ni * 8 + gid][kt * 8 + tig + 4]);
                MMA_TF32(sf[ni], qf[kt], bf);
            }
        }

        // ---- mask + scale + online softmax ----
        float mnew0 = mrun0, mnew1 = mrun1;
#pragma unroll
        for (int ni = 0; ni < 8; ni++) {
            int c = ni * 8 + 2 * tig;
            bool m0 = mt[c] == 1, m1 = mt[c + 1] == 1;
            sf[ni][0] = m0 ? -1e9f : sf[ni][0] * 0.125f;
            sf[ni][1] = m1 ? -1e9f : sf[ni][1] * 0.125f;
            sf[ni][2] = m0 ? -1e9f : sf[ni][2] * 0.125f;
            sf[ni][3] = m1 ? -1e9f : sf[ni][3] * 0.125f;
            mnew0 = fmaxf(mnew0, fmaxf(sf[ni][0], sf[ni][1]));
            mnew1 = fmaxf(mnew1, fmaxf(sf[ni][2], sf[ni][3]));
        }
        mnew0 = fmaxf(mnew0, __shfl_xor_sync(0xffffffffu, mnew0, 1));
        mnew0 = fmaxf(mnew0, __shfl_xor_sync(0xffffffffu, mnew0, 2));
        mnew1 = fmaxf(mnew1, __shfl_xor_sync(0xffffffffu, mnew1, 1));
        mnew1 = fmaxf(mnew1, __shfl_xor_sync(0xffffffffu, mnew1, 2));
        float alpha0 = __expf(mrun0 - mnew0);
        float alpha1 = __expf(mrun1 - mnew1);
        mrun0 = mnew0; mrun1 = mnew1;

        float rs0 = 0.f, rs1 = 0.f;
#pragma unroll
        for (int ni = 0; ni < 8; ni++) {
            sf[ni][0] = __expf(sf[ni][0] - mnew0);
            sf[ni][1] = __expf(sf[ni][1] - mnew0);
            sf[ni][2] = __expf(sf[ni][2] - mnew1);
            sf[ni][3] = __expf(sf[ni][3] - mnew1);
            rs0 += sf[ni][0] + sf[ni][1];
            rs1 += sf[ni][2] + sf[ni][3];
        }
        rs0 += __shfl_xor_sync(0xffffffffu, rs0, 1);
        rs0 += __shfl_xor_sync(0xffffffffu, rs0, 2);
        rs1 += __shfl_xor_sync(0xffffffffu, rs1, 1);
        rs1 += __shfl_xor_sync(0xffffffffu, rs1, 2);
        lrun0 = lrun0 * alpha0 + rs0;
        lrun1 = lrun1 * alpha1 + rs1;
#pragma unroll
        for (int ni = 0; ni < 8; ni++) {
            of[ni][0] *= alpha0; of[ni][1] *= alpha0;
            of[ni][2] *= alpha1; of[ni][3] *= alpha1;
        }

        // ---- write P (tf32) to own rows of Ps ----
        {
            int r0 = wid * 16 + gid;
#pragma unroll
            for (int ni = 0; ni < 8; ni++) {
                int c = ni * 8 + 2 * tig;
                uint2 u0 = { f2tf(sf[ni][0]), f2tf(sf[ni][1]) };
                *(uint2*)(&Ps[r0][c]) = u0;
                uint2 u1 = { f2tf(sf[ni][2]), f2tf(sf[ni][3]) };
                *(uint2*)(&Ps[r0 + 8][c]) = u1;
            }
        }

        // ---- O += P @ V (reads only this warp's P rows) ----
        {
            int m = wid * 16 + gid;
#pragma unroll
            for (int kt = 0; kt < 8; kt++) {
                uint32_t a[4];
                a[0] = Ps[m][kt * 8 + tig];
                a[1] = Ps[m + 8][kt * 8 + tig];
                a[2] = Ps[m][kt * 8 + tig + 4];
                a[3] = Ps[m + 8][kt * 8 + tig + 4];
#pragma unroll
                for (int ni = 0; ni < 8; ni++) {
                    uint32_t bf[2];
                    bf[0] = f2tf(Vf[kt * 8 + tig][ni * 8 + gid]);
                    bf[1] = f2tf(Vf[kt * 8 + tig + 4][ni * 8 + gid]);
                    MMA_TF32(of[ni], a, bf);
                }
            }
        }
        __syncthreads();   // all reads of this K/V buffer done before overwrite
    }

    // ---- epilogue: O /= l, write to att ----
    float inv0 = 1.f / lrun0;
    float inv1 = 1.f / lrun1;
    int r0 = s0 + wid * 16 + gid;
#pragma unroll
    for (int ni = 0; ni < 8; ni++) {
        int c = h * 64 + ni * 8 + 2 * tig;
        float2 v0 = { of[ni][0] * inv0, of[ni][1] * inv0 };
        *(float2*)(att + (size_t)(b * SS + r0) * DD + c) = v0;
        float2 v1 = { of[ni][2] * inv1, of[ni][3] * inv1 };
        *(float2*)(att + (size_t)(b * SS + r0 + 8) * DD + c) = v1;
    }
}

// ---------------- final head: LN(x[:,0,:]) @ cls_w + cls_b ------------------------
__global__ __launch_bounds__(256) void head_kernel(const float* __restrict__ x,
                                                   const float* __restrict__ hs,
                                                   const float* __restrict__ hb,
                                                   const float* __restrict__ cw,
                                                   const float* __restrict__ cb,
                                                   float* __restrict__ out) {
    int b = blockIdx.x;
    int tid = threadIdx.x;
    const float* p = x + (size_t)b * SS * DD;   // s = 0 row
    float v0 = p[tid], v1 = p[tid + 256], v2 = p[tid + 512];
    __shared__ float rs[256], rq[256];
    rs[tid] = v0 + v1 + v2;
    rq[tid] = v0 * v0 + v1 * v1 + v2 * v2;
    __syncthreads();
    for (int st = 128; st > 0; st >>= 1) {
        if (tid < st) { rs[tid] += rs[tid + st]; rq[tid] += rq[tid + st]; }
        __syncthreads();
    }
    float mean = rs[0] * (1.0f / DD);
    float var  = rq[0] * (1.0f / DD) - mean * mean;
    float inv  = rsqrtf(var + 1e-5f);
    float p0 = (v0 - mean) * inv * hs[tid]       + hb[tid];
    float p1 = (v1 - mean) * inv * hs[tid + 256] + hb[tid + 256];
    float p2 = (v2 - mean) * inv * hs[tid + 512] + hb[tid + 512];
    float d0 = p0 * cw[2 * tid]     + p1 * cw[2 * (tid + 256)]     + p2 * cw[2 * (tid + 512)];
    float d1 = p0 * cw[2 * tid + 1] + p1 * cw[2 * (tid + 256) + 1] + p2 * cw[2 * (tid + 512) + 1];
    __syncthreads();
    rs[tid] = d0; rq[tid] = d1;
    __syncthreads();
    for (int st = 128; st > 0; st >>= 1) {
        if (tid < st) { rs[tid] += rs[tid + st]; rq[tid] += rq[tid + st]; }
        __syncthreads();
    }
    if (tid == 0) {
        out[2 * b]     = rs[0] + cb[0];
        out[2 * b + 1] = rq[0] + cb[1];
    }
}

// ---------------- host orchestration ---------------------------------------------
extern "C" void kernel_launch(void* const* d_in, const int* in_sizes, int n_in,
                              void* d_out, int out_size) {
    const int*   input_ids = (const int*)d_in[0];
    const int*   attn_mask = (const int*)d_in[1];
    const float* token_emb = (const float*)d_in[2];
    const float* pos_emb   = (const float*)d_in[3];
    const float* qkv_w     = (const float*)d_in[4];
    const float* qkv_b     = (const float*)d_in[5];
    const float* out_w     = (const float*)d_in[6];
    const float* out_b     = (const float*)d_in[7];
    const float* n1_s      = (const float*)d_in[8];
    const float* n1_b      = (const float*)d_in[9];
    const float* ff1_w     = (const float*)d_in[10];
    const float* ff1_b     = (const float*)d_in[11];
    const float* ff2_w     = (const float*)d_in[12];
    const float* ff2_b     = (const float*)d_in[13];
    const float* n2_s      = (const float*)d_in[14];
    const float* n2_b      = (const float*)d_in[15];
    const float* hln_s     = (const float*)d_in[16];
    const float* hln_b     = (const float*)d_in[17];
    const float* cls_w     = (const float*)d_in[18];
    const float* cls_b     = (const float*)d_in[19];
    float* out = (float*)d_out;

    float *x, *h, *qkv, *att, *ff;
    cudaGetSymbolAddress((void**)&x,   g_x);
    cudaGetSymbolAddress((void**)&h,   g_h);
    cudaGetSymbolAddress((void**)&qkv, g_qkv);
    cudaGetSymbolAddress((void**)&att, g_att);
    cudaGetSymbolAddress((void**)&ff,  g_ff);

    cudaFuncSetAttribute(fattn_kernel,
                         cudaFuncAttributeMaxDynamicSharedMemorySize, FA_SMEM);
    cudaFuncSetAttribute(tgemm2<false, false>,
                         cudaFuncAttributeMaxDynamicSharedMemorySize, TG_SMEM);
    cudaFuncSetAttribute(tgemm2<false, true>,
                         cudaFuncAttributeMaxDynamicSharedMemorySize, TG_SMEM);
    cudaFuncSetAttribute(tgemm2<true, false>,
                         cudaFuncAttributeMaxDynamicSharedMemorySize, TG_SMEM);

    embed_kernel<<<(NROWS * DD + 255) / 256, 256>>>(input_ids, token_emb, pos_emb, x);

    for (int i = 0; i < LL; i++) {
        ln_kernel<<<NROWS, 256>>>(x, n1_s + i * DD, n1_b + i * DD, h);
        // QKV projection: [8192,768] @ [768,2304]
        tgemm2<false, false><<<dim3(TD / 128, NROWS / 128), 256, TG_SMEM>>>(
            h, qkv_w + (size_t)i * DD * TD, qkv_b + i * TD, nullptr, qkv, DD, TD);
        // fused attention: scores + softmax + P@V, no DRAM score tensor
        fattn_kernel<<<dim3(SS / 128, BB * HH), 256, FA_SMEM>>>(qkv, attn_mask, att);
        // out projection + residual
        tgemm2<false, true><<<dim3(DD / 128, NROWS / 128), 256, TG_SMEM>>>(
            att, out_w + (size_t)i * DD * DD, out_b + i * DD, x, x, DD, DD);
        ln_kernel<<<NROWS, 256>>>(x, n2_s + i * DD, n2_b + i * DD, h);
        // FF1 + relu
        tgemm2<true, false><<<dim3(DF / 128, NROWS / 128), 256, TG_SMEM>>>(
            h, ff1_w + (size_t)i * DD * DF, ff1_b + i * DF, nullptr, ff, DD, DF);
        // FF2 + residual
        tgemm2<false, true><<<dim3(DD / 128, NROWS / 128), 256, TG_SMEM>>>(
            ff, ff2_w + (size_t)i * DF * DD, ff2_b + i * DD, x, x, DF, DD);
    }

    head_kernel<<<BB, 256>>>(x, hln_s, hln_b, cls_w, cls_b, out);
}